// round 12
// baseline (speedup 1.0000x reference)
#include <cuda_runtime.h>

// Gray-Scott reaction-diffusion residual, v12 = v4 + L2 prefetch of upcoming planes.
// y-march (chunked) + float2 in z. prefetch.global.L2 has no register/scoreboard
// cost: it adds DRAM bytes-in-flight for free so demand loads become L2 hits.
// Input:  output [50, 2, 100, 100, 100] fp32  (d_in[0])
// Output: f_u (48,96,96,96) then f_v (48,96,96,96), fp32.

#define SLICE_C  1000000      // 100^3
#define STRIDE_T 2000000      // 2 channels
#define PLANE    10000        // 100*100
#define ROW      100
#define OUTE     96
#define OUTP     (96*96)      // 9216
#define OUTVOL   (96*96*96)   // 884736
#define YCHUNK   24           // y steps per block (96/4)
#define PFDIST   8            // prefetch planes this far ahead of the y-march

__device__ __forceinline__ void pf_l2(const float* p) {
    asm volatile("prefetch.global.L2 [%0];" :: "l"(p));
}

__global__ void __launch_bounds__(192) gs_residual_v12(
    const float* __restrict__ in, float* __restrict__ out)
{
    const int zp = threadIdx.x;                    // 0..47 (z pair)
    const int z  = zp * 2;                         // output z (even)
    const int x  = blockIdx.x * 4 + threadIdx.y;   // 0..95
    const int yb = blockIdx.y * YCHUNK;            // output y chunk start
    const int t  = blockIdx.z;                     // 0..47

    const float* __restrict__ u = in + (long long)t * STRIDE_T;
    const float* __restrict__ v = u + SLICE_C;
    const float* __restrict__ un_p = u + STRIDE_T;   // t+1, channel u
    const float* __restrict__ vn_p = v + STRIDE_T;   // t+1, channel v

    // offset of the center float2 within an input y-plane (covers input z+2, z+3)
    const int base = (x + 2) * ROW + (z + 2);

    const float S0 = -1.0f / 12.0f;
    const float S1 = 4.0f / 3.0f;
    const float SC = -7.5f;
    const float DXv = 100.0f / 48.0f;
    const float INV_DX2 = 1.0f / (DXv * DXv);
    const float INV_DT = 2.0f;               // 1/0.5
    const float DU = 0.2f, DV = 0.1f, FF = 0.025f, KK = 0.055f;

    // register queue of center float2s for input planes yb .. yb+3
    float2 qu[5], qv[5];
#pragma unroll
    for (int i = 0; i < 4; i++) {
        qu[i] = *(const float2*)(u + (yb + i) * PLANE + base);
        qv[i] = *(const float2*)(v + (yb + i) * PLANE + base);
    }

    int oidx = t * OUTVOL + yb * OUTP + x * OUTE + z;   // output index for yc=yb

#pragma unroll 2
    for (int yy = 0; yy < YCHUNK; yy++) {
        const int yc = yb + yy;
        const int pc = (yc + 2) * PLANE + base;   // center plane index

        // ---- L2 prefetch: planes PFDIST ahead of the march (no reg/SB cost).
        // All addresses verified in-bounds for worst case (t=47, yc=95).
        {
            const int pp = (yc + PFDIST) * PLANE + base;
            pf_l2(u + pp);        // u(t) plane y+PFDIST
            pf_l2(v + pp);        // v(t)
            pf_l2(un_p + pp);     // u(t+1)
            pf_l2(vn_p + pp);     // v(t+1)
        }

        // new far-plane centers (y+4)
        qu[4] = *(const float2*)(u + (yc + 4) * PLANE + base);
        qv[4] = *(const float2*)(v + (yc + 4) * PLANE + base);

        // z-halo: left = inputs z, z+1 ; right = inputs z+4, z+5
        float2 uzl = *(const float2*)(u + pc - 2);
        float2 uzr = *(const float2*)(u + pc + 2);
        float2 vzl = *(const float2*)(v + pc - 2);
        float2 vzr = *(const float2*)(v + pc + 2);

        // x taps
        float2 uxm1 = *(const float2*)(u + pc - ROW);
        float2 uxp1 = *(const float2*)(u + pc + ROW);
        float2 uxm2 = *(const float2*)(u + pc - 2 * ROW);
        float2 uxp2 = *(const float2*)(u + pc + 2 * ROW);
        float2 vxm1 = *(const float2*)(v + pc - ROW);
        float2 vxp1 = *(const float2*)(v + pc + ROW);
        float2 vxm2 = *(const float2*)(v + pc - 2 * ROW);
        float2 vxp2 = *(const float2*)(v + pc + 2 * ROW);

        // t+1 centers
        float2 unx = *(const float2*)(un_p + pc);
        float2 vnx = *(const float2*)(vn_p + pc);

        float2 uc = qu[2];
        float2 vc = qv[2];

        // ---- u laplacian ----
        // point 0 (input z+2): z±1 = uzl.y, uc.y ; z±2 = uzl.x, uzr.x
        float s1u0 = uzl.y + uc.y + uxm1.x + uxp1.x + qu[1].x + qu[3].x;
        float s2u0 = uzl.x + uzr.x + uxm2.x + uxp2.x + qu[0].x + qu[4].x;
        // point 1 (input z+3): z±1 = uc.x, uzr.x ; z±2 = uzl.y, uzr.y
        float s1u1 = uc.x + uzr.x + uxm1.y + uxp1.y + qu[1].y + qu[3].y;
        float s2u1 = uzl.y + uzr.y + uxm2.y + uxp2.y + qu[0].y + qu[4].y;
        float lapu0 = (S1 * s1u0 + S0 * s2u0 + SC * uc.x) * INV_DX2;
        float lapu1 = (S1 * s1u1 + S0 * s2u1 + SC * uc.y) * INV_DX2;

        // ---- v laplacian ----
        float s1v0 = vzl.y + vc.y + vxm1.x + vxp1.x + qv[1].x + qv[3].x;
        float s2v0 = vzl.x + vzr.x + vxm2.x + vxp2.x + qv[0].x + qv[4].x;
        float s1v1 = vc.x + vzr.x + vxm1.y + vxp1.y + qv[1].y + qv[3].y;
        float s2v1 = vzl.y + vzr.y + vxm2.y + vxp2.y + qv[0].y + qv[4].y;
        float lapv0 = (S1 * s1v0 + S0 * s2v0 + SC * vc.x) * INV_DX2;
        float lapv1 = (S1 * s1v1 + S0 * s2v1 + SC * vc.y) * INV_DX2;

        // ---- reaction + time derivative ----
        float uvv0 = uc.x * vc.x * vc.x;
        float uvv1 = uc.y * vc.y * vc.y;
        float ut0 = (unx.x - uc.x) * INV_DT;
        float ut1 = (unx.y - uc.y) * INV_DT;
        float vt0 = (vnx.x - vc.x) * INV_DT;
        float vt1 = (vnx.y - vc.y) * INV_DT;

        float2 fu, fv;
        fu.x = DU * lapu0 - uvv0 + FF * (1.0f - uc.x) - ut0;
        fu.y = DU * lapu1 - uvv1 + FF * (1.0f - uc.y) - ut1;
        fv.x = DV * lapv0 + uvv0 - (FF + KK) * vc.x - vt0;
        fv.y = DV * lapv1 + uvv1 - (FF + KK) * vc.y - vt1;

        *(float2*)(out + oidx) = fu;
        *(float2*)(out + 48 * OUTVOL + oidx) = fv;
        oidx += OUTP;

        // shift queues
        qu[0] = qu[1]; qu[1] = qu[2]; qu[2] = qu[3]; qu[3] = qu[4];
        qv[0] = qv[1]; qv[1] = qv[2]; qv[2] = qv[3]; qv[3] = qv[4];
    }
}

extern "C" void kernel_launch(void* const* d_in, const int* in_sizes, int n_in,
                              void* d_out, int out_size)
{
    const float* in = (const float*)d_in[0];
    float* out = (float*)d_out;
    dim3 grid(24, 4, 48);    // x-tiles (96/4), y-chunks, t
    dim3 block(48, 4);       // z-pairs, x within tile
    gs_residual_v12<<<grid, block>>>(in, out);
}